// round 13
// baseline (speedup 1.0000x reference)
#include <cuda_runtime.h>
#include <math.h>

// Problem constants
#define B    8
#define S    2048
#define D    1024
#define NB   20
#define NCTA 128
#define EPS  1e-8f

// ---------------- static device scratch ----------------
__device__ float g_x  [B * S * D];
__device__ float g_wx [B * S * D];
__device__ float g_kx [B * S * NB];
__device__ float g_Ut [D * D];
__device__ float g_Vt [D * D];
__device__ float g_KV [NB * D];
__device__ float g_h  [B * NB * D];
__device__ float g_pre[B * NB * D];

__device__ unsigned g_bar_count = 0;
__device__ volatile unsigned g_bar_gen = 0;

// ---------------- f32x2 helpers ----------------
#define PACK2(DST, X, Y) \
    asm("mov.b64 %0, {%1, %2};" : "=l"(DST) : "f"(X), "f"(Y))

// acc pair (4 cols) += (h,h) * (u01, u23)
#define FM2(A01, A23, H, UA, UB) do {                                   \
    unsigned long long hh_;                                             \
    asm("mov.b64 %0, {%1, %1};" : "=l"(hh_) : "f"(H));                  \
    asm("fma.rn.f32x2 %0, %1, %2, %0;" : "+l"(A01) : "l"(hh_), "l"(UA));\
    asm("fma.rn.f32x2 %0, %1, %2, %0;" : "+l"(A23) : "l"(hh_), "l"(UB));\
} while (0)

__device__ __forceinline__ float2 ull2f2(unsigned long long v) {
    float2 r;
    asm("mov.b64 {%0, %1}, %2;" : "=f"(r.x), "=f"(r.y) : "l"(v));
    return r;
}

// ---------------- grid barrier (software, persistent kernel) ----------------
__device__ __forceinline__ void grid_barrier() {
    __threadfence();           // release all stores + invalidate L1 (gpu scope)
    __syncthreads();
    if (threadIdx.x == 0) {
        unsigned g = g_bar_gen;
        if (atomicAdd(&g_bar_count, 1u) == NCTA - 1) {
            atomicExch(&g_bar_count, 0u);
            __threadfence();
            g_bar_gen = g + 1u;
        } else {
            while (g_bar_gen == g) { }
        }
    }
    __syncthreads();
}

// ---------------- precompute kernels ----------------
__global__ __launch_bounds__(256) void k_init_h(const float* __restrict__ state) {
    int s = blockIdx.x, b = blockIdx.y;
    ((float4*)(g_h + (b * NB + s) * D))[threadIdx.x] =
        ((const float4*)(state + s * D))[threadIdx.x];
}

__global__ __launch_bounds__(256) void k_prep_x(const float* __restrict__ e,
                                                const float* __restrict__ m,
                                                const float* __restrict__ keys) {
    int t = blockIdx.x, b = blockIdx.y;
    int tid = threadIdx.x;
    __shared__ float xs[D];
    int base = (b * S + t) * D;
    float4 ev = ((const float4*)(e + base))[tid];
    float4 mv = ((const float4*)(m + base))[tid];
    float4 xv;
    xv.x = ev.x + mv.x; xv.y = ev.y + mv.y;
    xv.z = ev.z + mv.z; xv.w = ev.w + mv.w;
    ((float4*)(g_x + base))[tid] = xv;
    ((float4*)xs)[tid] = xv;
    __syncthreads();
    int w = tid >> 5, l = tid & 31;
    for (int s = w; s < NB; s += 8) {
        const float* kr = keys + s * D;
        float a = 0.f;
        for (int i = l; i < D; i += 32) a += kr[i] * xs[i];
        #pragma unroll
        for (int o = 16; o; o >>= 1) a += __shfl_down_sync(0xffffffffu, a, o);
        if (l == 0) g_kx[(b * S + t) * NB + s] = a;
    }
}

__global__ void k_transpose(const float* __restrict__ U, const float* __restrict__ V) {
    __shared__ float tile[32][33];
    const float* src = blockIdx.z ? V : U;
    float* dst = blockIdx.z ? g_Vt : g_Ut;
    int x0 = blockIdx.x * 32, y0 = blockIdx.y * 32;
    int tx = threadIdx.x, ty = threadIdx.y;
    #pragma unroll
    for (int i = 0; i < 32; i += 8)
        tile[ty + i][tx] = src[(y0 + ty + i) * D + x0 + tx];
    __syncthreads();
    #pragma unroll
    for (int i = 0; i < 32; i += 8)
        dst[(x0 + ty + i) * D + y0 + tx] = tile[tx][ty + i];
}

__global__ __launch_bounds__(128) void k_kv(const float* __restrict__ keys) {
    int s = blockIdx.y;
    int d = blockIdx.x * 128 + threadIdx.x;
    float acc = 0.f;
    const float* kr = keys + s * D;
    #pragma unroll 4
    for (int k = 0; k < D; k++) acc += kr[k] * g_Vt[k * D + d];
    g_KV[s * D + d] = acc;
}

// g_wx[row][d] = sum_k g_x[row][k] * W[d][k]
#define BM 64
#define BN 64
#define BK 32
#define PAD 4
__global__ __launch_bounds__(256) void k_wx_gemm(const float* __restrict__ W) {
    int n0 = blockIdx.x * BN;
    int m0 = blockIdx.y * BM;
    __shared__ float Xs[BK][BM + PAD];
    __shared__ float Ws[BK][BN + PAD];
    int tid = threadIdx.x;
    int tx = tid & 15, ty = tid >> 4;
    float acc[4][4];
    #pragma unroll
    for (int r = 0; r < 4; r++)
        #pragma unroll
        for (int c = 0; c < 4; c++) acc[r][c] = 0.f;

    for (int k0 = 0; k0 < D; k0 += BK) {
        #pragma unroll
        for (int i = 0; i < 2; i++) {
            int f = tid + i * 256;
            int r = f >> 3, kq = (f & 7) * 4;
            float4 xv = *(const float4*)(g_x + (m0 + r) * D + k0 + kq);
            Xs[kq + 0][r] = xv.x; Xs[kq + 1][r] = xv.y;
            Xs[kq + 2][r] = xv.z; Xs[kq + 3][r] = xv.w;
            float4 wv = *(const float4*)(W + (n0 + r) * D + k0 + kq);
            Ws[kq + 0][r] = wv.x; Ws[kq + 1][r] = wv.y;
            Ws[kq + 2][r] = wv.z; Ws[kq + 3][r] = wv.w;
        }
        __syncthreads();
        #pragma unroll
        for (int k = 0; k < BK; k++) {
            float4 a  = *(const float4*)&Xs[k][ty * 4];
            float4 bq = *(const float4*)&Ws[k][tx * 4];
            float ar[4] = {a.x, a.y, a.z, a.w};
            float br[4] = {bq.x, bq.y, bq.z, bq.w};
            #pragma unroll
            for (int r = 0; r < 4; r++)
                #pragma unroll
                for (int c = 0; c < 4; c++)
                    acc[r][c] = fmaf(ar[r], br[c], acc[r][c]);
        }
        __syncthreads();
    }
    #pragma unroll
    for (int r = 0; r < 4; r++) {
        float4 o = {acc[r][0], acc[r][1], acc[r][2], acc[r][3]};
        *(float4*)(g_wx + (m0 + ty * 4 + r) * D + n0 + tx * 4) = o;
    }
}

// ---------------- phase 2: gate / tanh / update / normalize one row ----------------
__device__ __forceinline__ void update_row(int r, int t, float* __restrict__ out,
                                           float* s_r8, float* s_bc) {
    int tid = threadIdx.x, l = tid & 31, w = tid >> 5;
    int b = r / NB;                 // row r = b*NB + slot
    int slot = r - b * NB;

    float4* hrow = (float4*)(g_h + r * D);
    float4 hv = hrow[tid];
    float4 xv = ((const float4*)(g_x + (b * S + t) * D))[tid];

    float p = hv.x * xv.x + hv.y * xv.y + hv.z * xv.z + hv.w * xv.w;
    #pragma unroll
    for (int o = 16; o; o >>= 1) p += __shfl_down_sync(0xffffffffu, p, o);
    if (l == 0) s_r8[w] = p;
    __syncthreads();
    if (tid < 8) {
        float v = s_r8[tid];
        v += __shfl_down_sync(0xffu, v, 4);
        v += __shfl_down_sync(0xffu, v, 2);
        v += __shfl_down_sync(0xffu, v, 1);
        if (tid == 0) {
            float z = v + g_kx[(b * S + t) * NB + slot];
            s_bc[0] = 1.0f / (1.0f + expf(-z));
        }
    }
    __syncthreads();
    float g = s_bc[0];

    float4 pv = ((const float4*)(g_pre + r * D))[tid];
    float4 hn;
    hn.x = hv.x + g * tanhf(pv.x);
    hn.y = hv.y + g * tanhf(pv.y);
    hn.z = hv.z + g * tanhf(pv.z);
    hn.w = hv.w + g * tanhf(pv.w);

    float q = hn.x * hn.x + hn.y * hn.y + hn.z * hn.z + hn.w * hn.w;
    #pragma unroll
    for (int o = 16; o; o >>= 1) q += __shfl_down_sync(0xffffffffu, q, o);
    if (l == 0) s_r8[w] = q;
    __syncthreads();
    if (tid < 8) {
        float v = s_r8[tid];
        v += __shfl_down_sync(0xffu, v, 4);
        v += __shfl_down_sync(0xffu, v, 2);
        v += __shfl_down_sync(0xffu, v, 1);
        if (tid == 0) s_bc[1] = 1.0f / (sqrtf(v) + EPS);
    }
    __syncthreads();
    float inv = s_bc[1];
    hn.x *= inv; hn.y *= inv; hn.z *= inv; hn.w *= inv;
    hrow[tid] = hn;
    if (t == S - 1) ((float4*)out)[r * (D / 4) + tid] = hn;
}

// ---------------- persistent scan kernel ----------------
// 128 CTAs x 256 threads, all co-resident (148 SMs).
// phase1 CTA role: cg = colgroup (8 x 128 cols), b = batch, sh = slot-half (10 slots)
// phase1 warp role: k-eighth (128 k). lane owns 4 cols (float4).
// phase2 CTA role: rows r = cta, and r = 128+cta for cta < 32.
__global__ __launch_bounds__(256, 1) void k_scan(float* __restrict__ out) {
    const int tid = threadIdx.x;
    const int w = tid >> 5, l = tid & 31;
    const int cta = blockIdx.x;
    const int cg = cta & 7;
    const int b  = (cta >> 3) & 7;
    const int sh = cta >> 6;

    const int c0 = cg * 128 + l * 4;
    const int k0 = w * 128;

    __shared__ float4 s_red[8][10][32];   // [warp][slot][lane] 40 KB
    __shared__ float  s_r8[8];
    __shared__ float  s_bc[2];

    const float* up_base = g_Ut + k0 * D + c0;
    const float* hp_base = g_h + (b * NB + sh * 10) * D + k0;

    const int r2 = (cta < 32) ? (128 + cta) : -1;

    for (int t = 0; t < S; t++) {
        // ===== phase 1: pre = h @ U^T + KV + Wx =====
        unsigned long long a01[10], a23[10];
        #pragma unroll
        for (int j = 0; j < 10; j++) { a01[j] = 0ULL; a23[j] = 0ULL; }

        #pragma unroll 2
        for (int kk = 0; kk < 128; kk += 4) {
            const float* up = up_base + kk * D;
            float4 u0 = *(const float4*)(up);
            float4 u1 = *(const float4*)(up + D);
            float4 u2 = *(const float4*)(up + 2 * D);
            float4 u3 = *(const float4*)(up + 3 * D);
            unsigned long long u0a, u0b, u1a, u1b, u2a, u2b, u3a, u3b;
            PACK2(u0a, u0.x, u0.y); PACK2(u0b, u0.z, u0.w);
            PACK2(u1a, u1.x, u1.y); PACK2(u1b, u1.z, u1.w);
            PACK2(u2a, u2.x, u2.y); PACK2(u2b, u2.z, u2.w);
            PACK2(u3a, u3.x, u3.y); PACK2(u3b, u3.z, u3.w);
            #pragma unroll
            for (int j = 0; j < 10; j++) {
                float4 hv = *(const float4*)(hp_base + j * D + kk);  // warp-uniform
                FM2(a01[j], a23[j], hv.x, u0a, u0b);
                FM2(a01[j], a23[j], hv.y, u1a, u1b);
                FM2(a01[j], a23[j], hv.z, u2a, u2b);
                FM2(a01[j], a23[j], hv.w, u3a, u3b);
            }
        }

        // cross-warp k-reduction in smem
        #pragma unroll
        for (int j = 0; j < 10; j++) {
            float2 f01 = ull2f2(a01[j]);
            float2 f23 = ull2f2(a23[j]);
            s_red[w][j][l] = make_float4(f01.x, f01.y, f23.x, f23.y);
        }
        __syncthreads();

        const int trowD = (b * S + t) * D;
        for (int o = tid; o < 320; o += 256) {
            int j = o >> 5, lane = o & 31;
            float4 s = s_red[0][j][lane];
            #pragma unroll
            for (int ww = 1; ww < 8; ww++) {
                float4 v = s_red[ww][j][lane];
                s.x += v.x; s.y += v.y; s.z += v.z; s.w += v.w;
            }
            int slot = sh * 10 + j;
            int c = cg * 128 + lane * 4;
            float4 kv = *(const float4*)(g_KV + slot * D + c);
            float4 wx = *(const float4*)(g_wx + trowD + c);
            float4 o4;
            o4.x = s.x + kv.x + wx.x;
            o4.y = s.y + kv.y + wx.y;
            o4.z = s.z + kv.z + wx.z;
            o4.w = s.w + kv.w + wx.w;
            *(float4*)(g_pre + (b * NB + slot) * D + c) = o4;
        }

        grid_barrier();

        // ===== phase 2: gate / tanh / update / normalize =====
        update_row(cta, t, out, s_r8, s_bc);
        if (r2 >= 0) update_row(r2, t, out, s_r8, s_bc);

        grid_barrier();
    }
}

// ---------------- launch ----------------
extern "C" void kernel_launch(void* const* d_in, const int* in_sizes, int n_in,
                              void* d_out, int out_size) {
    const float* e     = (const float*)d_in[0];
    const float* m     = (const float*)d_in[1];
    const float* state = (const float*)d_in[2];
    const float* U     = (const float*)d_in[3];
    const float* V     = (const float*)d_in[4];
    const float* W     = (const float*)d_in[5];
    const float* keys  = (const float*)d_in[6];
    float* out = (float*)d_out;

    k_init_h   <<<dim3(NB, B), 256>>>(state);
    k_prep_x   <<<dim3(S, B), 256>>>(e, m, keys);
    k_transpose<<<dim3(32, 32, 2), dim3(32, 8)>>>(U, V);
    k_kv       <<<dim3(D / 128, NB), 128>>>(keys);
    k_wx_gemm  <<<dim3(D / BN, (B * S) / BM), 256>>>(W);
    k_scan     <<<NCTA, 256>>>(out);
}